// round 2
// baseline (speedup 1.0000x reference)
#include <cuda_runtime.h>

#define H_LR 512
#define W_LR 512
#define H_HR 2048
#define W_HR 2048
#define PLANES 12
#define EPS_F 0.01f

// Scratch for mean_A / mean_b at low resolution (alloc-free: __device__ globals)
__device__ float g_meanA[PLANES * H_LR * W_LR];
__device__ float g_meanB[PLANES * H_LR * W_LR];

#define TILE 32
#define SM_W 36   // TILE + 4 (2-pixel halo each side for double 3x3)
#define SM_A 34   // TILE + 2 (1-pixel apron of A/b)
#define SSTR 37   // row stride, avoids bank conflicts

__global__ __launch_bounds__(256)
void k1_ab_mean(const float* __restrict__ x, const float* __restrict__ y) {
    __shared__ float sx[SM_W * SSTR];
    __shared__ float sy[SM_W * SSTR];
    __shared__ float sA[SM_A * SSTR];
    __shared__ float sB[SM_A * SSTR];

    const int plane = blockIdx.z;
    const int gy0 = blockIdx.y * TILE;
    const int gx0 = blockIdx.x * TILE;
    const float* __restrict__ xp = x + (size_t)plane * (H_LR * W_LR);
    const float* __restrict__ yp = y + (size_t)plane * (H_LR * W_LR);
    const int t = threadIdx.y * 32 + threadIdx.x;
    const float inv9 = 1.0f / 9.0f;

    // Phase 1: load 36x36 halo with edge clamp
    for (int idx = t; idx < SM_W * SM_W; idx += 256) {
        int i = idx / SM_W, j = idx - i * SM_W;
        int gy = min(max(gy0 - 2 + i, 0), H_LR - 1);
        int gx = min(max(gx0 - 2 + j, 0), W_LR - 1);
        sx[i * SSTR + j] = xp[gy * W_LR + gx];
        sy[i * SSTR + j] = yp[gy * W_LR + gx];
    }
    __syncthreads();

    // Phase 2: compute A, b on the 34x34 apron, TWO horizontal outputs per
    // thread sharing a 3x4 tap window. A/b are evaluated at CLAMPED global
    // pixel coords (== replication padding of A for the second boxfilter).
    for (int idx = t; idx < SM_A * 17; idx += 256) {
        int i = idx / 17;
        int jp = idx - i * 17;
        int j0 = jp * 2;

        int py = min(max(gy0 - 1 + i, 0), H_LR - 1);
        int si = py - gy0 + 2;                       // [1,34]
        int px0 = min(max(gx0 - 1 + j0, 0), W_LR - 1);
        int px1 = min(max(gx0 + j0, 0), W_LR - 1);   // (gx0-1) + (j0+1)
        int sj0 = px0 - gx0 + 2;
        int sj1 = px1 - gx0 + 2;

        float cxs[4], cys[4], cxys[4], cxxs[4];
        #pragma unroll
        for (int c = 0; c < 4; c++) {
            int col = (c < 3) ? (sj0 - 1 + c) : (sj1 + 1);
            float xs = 0.f, ys = 0.f, xys = 0.f, xxs = 0.f;
            #pragma unroll
            for (int r = 0; r < 3; r++) {
                float xv = sx[(si - 1 + r) * SSTR + col];
                float yv = sy[(si - 1 + r) * SSTR + col];
                xs += xv; ys += yv;
                xys = fmaf(xv, yv, xys);
                xxs = fmaf(xv, xv, xxs);
            }
            cxs[c] = xs; cys[c] = ys; cxys[c] = xys; cxxs[c] = xxs;
        }

        bool two = (sj1 > sj0);
        float s0x  = cxs[0] + cxs[1] + cxs[2];
        float s0y  = cys[0] + cys[1] + cys[2];
        float s0xy = cxys[0] + cxys[1] + cxys[2];
        float s0xx = cxxs[0] + cxxs[1] + cxxs[2];
        float s1x  = two ? (cxs[1] + cxs[2] + cxs[3])   : s0x;
        float s1y  = two ? (cys[1] + cys[2] + cys[3])   : s0y;
        float s1xy = two ? (cxys[1] + cxys[2] + cxys[3]) : s0xy;
        float s1xx = two ? (cxxs[1] + cxxs[2] + cxxs[3]) : s0xx;

        float mx0 = s0x * inv9, my0 = s0y * inv9;
        float cov0 = s0xy * inv9 - mx0 * my0;
        float var0 = s0xx * inv9 - mx0 * mx0;
        float A0 = __fdividef(cov0, var0 + EPS_F);
        float B0 = my0 - A0 * mx0;

        float mx1 = s1x * inv9, my1 = s1y * inv9;
        float cov1 = s1xy * inv9 - mx1 * my1;
        float var1 = s1xx * inv9 - mx1 * mx1;
        float A1 = __fdividef(cov1, var1 + EPS_F);
        float B1 = my1 - A1 * mx1;

        sA[i * SSTR + j0] = A0;
        sB[i * SSTR + j0] = B0;
        sA[i * SSTR + j0 + 1] = A1;
        sB[i * SSTR + j0 + 1] = B1;
    }
    __syncthreads();

    // Phase 3a: horizontal 3-tap over A/b, store into reused sx/sy
    for (int idx = t; idx < SM_A * TILE; idx += 256) {
        int i = idx / TILE, j = idx - i * TILE;
        int o = i * SSTR + j;
        sx[o] = sA[o] + sA[o + 1] + sA[o + 2];
        sy[o] = sB[o] + sB[o + 1] + sB[o + 2];
    }
    __syncthreads();

    // Phase 3b: vertical 3-tap -> mean_A, mean_b, write to scratch
    const int tx = threadIdx.x;
    for (int ty = threadIdx.y; ty < TILE; ty += 8) {
        float sa = (sx[ty * SSTR + tx] + sx[(ty + 1) * SSTR + tx] + sx[(ty + 2) * SSTR + tx]) * inv9;
        float sb = (sy[ty * SSTR + tx] + sy[(ty + 1) * SSTR + tx] + sy[(ty + 2) * SSTR + tx]) * inv9;
        int o = plane * (H_LR * W_LR) + (gy0 + ty) * W_LR + (gx0 + tx);
        g_meanA[o] = sa;
        g_meanB[o] = sb;
    }
}

// Kernel 2: one block per output row. Stage vertically-lerped Ac/Bc for all
// 512 low-res columns in SMEM (coalesced float4 loads), then each thread
// produces 8 output pixels with 4 LDS + lerp + affine + clip each.
__global__ __launch_bounds__(256)
void k2_upsample_apply(const float* __restrict__ xhr, float* __restrict__ out) {
    __shared__ float sAc[W_LR];
    __shared__ float sBc[W_LR];

    const float SCALE = 511.0f / 2047.0f;
    const int plane = blockIdx.y;
    const int oy = blockIdx.x;
    const int t = threadIdx.x;

    float posy = (float)oy * SCALE;
    int iy0 = (int)posy;
    float tyf = posy - (float)iy0;
    int iy1 = min(iy0 + 1, H_LR - 1);

    const size_t pl = (size_t)plane * (H_LR * W_LR);
    if (t < 128) {
        const float4* r0 = (const float4*)(g_meanA + pl + iy0 * W_LR);
        const float4* r1 = (const float4*)(g_meanA + pl + iy1 * W_LR);
        float4 a0 = r0[t], a1 = r1[t];
        float4 ac;
        ac.x = fmaf(tyf, a1.x - a0.x, a0.x);
        ac.y = fmaf(tyf, a1.y - a0.y, a0.y);
        ac.z = fmaf(tyf, a1.z - a0.z, a0.z);
        ac.w = fmaf(tyf, a1.w - a0.w, a0.w);
        ((float4*)sAc)[t] = ac;
    } else {
        int u = t - 128;
        const float4* r0 = (const float4*)(g_meanB + pl + iy0 * W_LR);
        const float4* r1 = (const float4*)(g_meanB + pl + iy1 * W_LR);
        float4 b0 = r0[u], b1 = r1[u];
        float4 bc;
        bc.x = fmaf(tyf, b1.x - b0.x, b0.x);
        bc.y = fmaf(tyf, b1.y - b0.y, b0.y);
        bc.z = fmaf(tyf, b1.z - b0.z, b0.z);
        bc.w = fmaf(tyf, b1.w - b0.w, b0.w);
        ((float4*)sBc)[u] = bc;
    }
    __syncthreads();

    const size_t base = (size_t)plane * (H_HR * W_HR) + (size_t)oy * W_HR;
    const float4* __restrict__ xin4 = (const float4*)(xhr + base);
    float4* __restrict__ out4 = (float4*)(out + base);

    #pragma unroll
    for (int half = 0; half < 2; half++) {
        int q = t * 2 + half;                 // float4 index 0..511
        float4 xv = xin4[q];
        float xin[4] = {xv.x, xv.y, xv.z, xv.w};
        float res[4];
        #pragma unroll
        for (int k = 0; k < 4; k++) {
            float posx = (float)(q * 4 + k) * SCALE;
            int jx = (int)posx;
            float txf = posx - (float)jx;
            int j1 = min(jx + 1, W_LR - 1);
            float a0 = sAc[jx], a1 = sAc[j1];
            float b0 = sBc[jx], b1 = sBc[j1];
            float aV = fmaf(txf, a1 - a0, a0);
            float bV = fmaf(txf, b1 - b0, b0);
            float r = fmaf(aV, xin[k], bV);
            res[k] = fminf(fmaxf(r, 0.0f), 255.0f);
        }
        out4[q] = make_float4(res[0], res[1], res[2], res[3]);
    }
}

extern "C" void kernel_launch(void* const* d_in, const int* in_sizes, int n_in,
                              void* d_out, int out_size) {
    const float* x_lr = (const float*)d_in[0];
    const float* y_lr = (const float*)d_in[1];
    const float* x_hr = (const float*)d_in[2];
    float* out = (float*)d_out;

    dim3 g1(W_LR / TILE, H_LR / TILE, PLANES);   // (16,16,12)
    dim3 b1(32, 8);
    k1_ab_mean<<<g1, b1>>>(x_lr, y_lr);

    dim3 g2(H_HR, PLANES);                       // one block per output row
    k2_upsample_apply<<<g2, 256>>>(x_hr, out);
}

// round 3
// speedup vs baseline: 1.0987x; 1.0987x over previous
#include <cuda_runtime.h>

#define H_LR 512
#define W_LR 512
#define H_HR 2048
#define W_HR 2048
#define PLANES 12
#define EPS_F 0.01f

// Scratch for mean_A / mean_b at low resolution (alloc-free: __device__ globals)
__device__ float g_meanA[PLANES * H_LR * W_LR];
__device__ float g_meanB[PLANES * H_LR * W_LR];

#define TILE 32
#define SM_W 36   // TILE + 4 (2-pixel halo each side for double 3x3)
#define SM_A 34   // TILE + 2 (1-pixel apron of A/b)
#define SSTR 37   // row stride, avoids bank conflicts

__global__ __launch_bounds__(256)
void k1_ab_mean(const float* __restrict__ x, const float* __restrict__ y) {
    __shared__ float sx[SM_W * SSTR];
    __shared__ float sy[SM_W * SSTR];
    __shared__ float sA[SM_A * SSTR];
    __shared__ float sB[SM_A * SSTR];

    const int plane = blockIdx.z;
    const int gy0 = blockIdx.y * TILE;
    const int gx0 = blockIdx.x * TILE;
    const float* __restrict__ xp = x + (size_t)plane * (H_LR * W_LR);
    const float* __restrict__ yp = y + (size_t)plane * (H_LR * W_LR);
    const int t = threadIdx.y * 32 + threadIdx.x;
    const float inv9 = 1.0f / 9.0f;

    // Phase 1: load 36x36 halo with edge clamp
    for (int idx = t; idx < SM_W * SM_W; idx += 256) {
        int i = idx / SM_W, j = idx - i * SM_W;
        int gy = min(max(gy0 - 2 + i, 0), H_LR - 1);
        int gx = min(max(gx0 - 2 + j, 0), W_LR - 1);
        sx[i * SSTR + j] = xp[gy * W_LR + gx];
        sy[i * SSTR + j] = yp[gy * W_LR + gx];
    }
    __syncthreads();

    // Phase 2: compute A, b on the 34x34 apron, TWO horizontal outputs per
    // thread sharing a 3x4 tap window. A/b are evaluated at CLAMPED global
    // pixel coords (== replication padding of A for the second boxfilter).
    for (int idx = t; idx < SM_A * 17; idx += 256) {
        int i = idx / 17;
        int jp = idx - i * 17;
        int j0 = jp * 2;

        int py = min(max(gy0 - 1 + i, 0), H_LR - 1);
        int si = py - gy0 + 2;                       // [1,34]
        int px0 = min(max(gx0 - 1 + j0, 0), W_LR - 1);
        int px1 = min(max(gx0 + j0, 0), W_LR - 1);   // (gx0-1) + (j0+1)
        int sj0 = px0 - gx0 + 2;
        int sj1 = px1 - gx0 + 2;

        float cxs[4], cys[4], cxys[4], cxxs[4];
        #pragma unroll
        for (int c = 0; c < 4; c++) {
            int col = (c < 3) ? (sj0 - 1 + c) : (sj1 + 1);
            float xs = 0.f, ys = 0.f, xys = 0.f, xxs = 0.f;
            #pragma unroll
            for (int r = 0; r < 3; r++) {
                float xv = sx[(si - 1 + r) * SSTR + col];
                float yv = sy[(si - 1 + r) * SSTR + col];
                xs += xv; ys += yv;
                xys = fmaf(xv, yv, xys);
                xxs = fmaf(xv, xv, xxs);
            }
            cxs[c] = xs; cys[c] = ys; cxys[c] = xys; cxxs[c] = xxs;
        }

        bool two = (sj1 > sj0);
        float s0x  = cxs[0] + cxs[1] + cxs[2];
        float s0y  = cys[0] + cys[1] + cys[2];
        float s0xy = cxys[0] + cxys[1] + cxys[2];
        float s0xx = cxxs[0] + cxxs[1] + cxxs[2];
        float s1x  = two ? (cxs[1] + cxs[2] + cxs[3])   : s0x;
        float s1y  = two ? (cys[1] + cys[2] + cys[3])   : s0y;
        float s1xy = two ? (cxys[1] + cxys[2] + cxys[3]) : s0xy;
        float s1xx = two ? (cxxs[1] + cxxs[2] + cxxs[3]) : s0xx;

        float mx0 = s0x * inv9, my0 = s0y * inv9;
        float cov0 = s0xy * inv9 - mx0 * my0;
        float var0 = s0xx * inv9 - mx0 * mx0;
        float A0 = __fdividef(cov0, var0 + EPS_F);
        float B0 = my0 - A0 * mx0;

        float mx1 = s1x * inv9, my1 = s1y * inv9;
        float cov1 = s1xy * inv9 - mx1 * my1;
        float var1 = s1xx * inv9 - mx1 * mx1;
        float A1 = __fdividef(cov1, var1 + EPS_F);
        float B1 = my1 - A1 * mx1;

        sA[i * SSTR + j0] = A0;
        sB[i * SSTR + j0] = B0;
        sA[i * SSTR + j0 + 1] = A1;
        sB[i * SSTR + j0 + 1] = B1;
    }
    __syncthreads();

    // Phase 3a: horizontal 3-tap over A/b, store into reused sx/sy
    for (int idx = t; idx < SM_A * TILE; idx += 256) {
        int i = idx / TILE, j = idx - i * TILE;
        int o = i * SSTR + j;
        sx[o] = sA[o] + sA[o + 1] + sA[o + 2];
        sy[o] = sB[o] + sB[o + 1] + sB[o + 2];
    }
    __syncthreads();

    // Phase 3b: vertical 3-tap -> mean_A, mean_b, write to scratch
    const int tx = threadIdx.x;
    for (int ty = threadIdx.y; ty < TILE; ty += 8) {
        float sa = (sx[ty * SSTR + tx] + sx[(ty + 1) * SSTR + tx] + sx[(ty + 2) * SSTR + tx]) * inv9;
        float sb = (sy[ty * SSTR + tx] + sy[(ty + 1) * SSTR + tx] + sy[(ty + 2) * SSTR + tx]) * inv9;
        int o = plane * (H_LR * W_LR) + (gy0 + ty) * W_LR + (gx0 + tx);
        g_meanA[o] = sa;
        g_meanB[o] = sb;
    }
}

// Kernel 2: one block per output row. Stage vertically-lerped Ac/Bc (512 each)
// in SMEM, then each thread produces 8 consecutive pixels. The 8-pixel group
// spans < 2 low-res units, so only columns jb..jb+3 are needed: 8 LDS per
// 8 pixels, cached in registers, horizontal lerp via 3-way selects.
__global__ __launch_bounds__(256)
void k2_upsample_apply(const float* __restrict__ xhr, float* __restrict__ out) {
    __shared__ float sAc[W_LR];
    __shared__ float sBc[W_LR];

    const float SCALE = 511.0f / 2047.0f;
    const int plane = blockIdx.y;
    const int oy = blockIdx.x;
    const int t = threadIdx.x;

    float posy = (float)oy * SCALE;
    int iy0 = (int)posy;
    float tyf = posy - (float)iy0;
    int iy1 = min(iy0 + 1, H_LR - 1);

    const size_t pl = (size_t)plane * (H_LR * W_LR);
    if (t < 128) {
        const float4* r0 = (const float4*)(g_meanA + pl + iy0 * W_LR);
        const float4* r1 = (const float4*)(g_meanA + pl + iy1 * W_LR);
        float4 a0 = r0[t], a1 = r1[t];
        float4 ac;
        ac.x = fmaf(tyf, a1.x - a0.x, a0.x);
        ac.y = fmaf(tyf, a1.y - a0.y, a0.y);
        ac.z = fmaf(tyf, a1.z - a0.z, a0.z);
        ac.w = fmaf(tyf, a1.w - a0.w, a0.w);
        ((float4*)sAc)[t] = ac;
    } else {
        int u = t - 128;
        const float4* r0 = (const float4*)(g_meanB + pl + iy0 * W_LR);
        const float4* r1 = (const float4*)(g_meanB + pl + iy1 * W_LR);
        float4 b0 = r0[u], b1 = r1[u];
        float4 bc;
        bc.x = fmaf(tyf, b1.x - b0.x, b0.x);
        bc.y = fmaf(tyf, b1.y - b0.y, b0.y);
        bc.z = fmaf(tyf, b1.z - b0.z, b0.z);
        bc.w = fmaf(tyf, b1.w - b0.w, b0.w);
        ((float4*)sBc)[u] = bc;
    }
    __syncthreads();

    const int ox0 = t * 8;
    float posx0 = (float)ox0 * SCALE;
    int jb = (int)posx0;
    float f0 = posx0 - (float)jb;          // in [0,1)

    // 4 columns cover the whole 8-pixel group (max offset jx+1 = jb+3)
    int j3 = min(jb + 3, W_LR - 1);
    float A0 = sAc[jb],     A1 = sAc[jb + 1], A2 = sAc[jb + 2], A3 = sAc[j3];
    float B0 = sBc[jb],     B1 = sBc[jb + 1], B2 = sBc[jb + 2], B3 = sBc[j3];

    const size_t base = (size_t)plane * (H_HR * W_HR) + (size_t)oy * W_HR;
    const float4* __restrict__ xin4 = (const float4*)(xhr + base);
    float4* __restrict__ out4 = (float4*)(out + base);

    #pragma unroll
    for (int half = 0; half < 2; half++) {
        int q = t * 2 + half;
        float4 xv = xin4[q];
        float xin[4] = {xv.x, xv.y, xv.z, xv.w};
        float res[4];
        #pragma unroll
        for (int k = 0; k < 4; k++) {
            int kk = half * 4 + k;
            float p = f0 + (float)kk * SCALE;   // in [0, 3)
            int off = (int)p;                    // 0, 1, or 2
            float txf = p - (float)off;
            float aLo = (off == 0) ? A0 : ((off == 1) ? A1 : A2);
            float aHi = (off == 0) ? A1 : ((off == 1) ? A2 : A3);
            float bLo = (off == 0) ? B0 : ((off == 1) ? B1 : B2);
            float bHi = (off == 0) ? B1 : ((off == 1) ? B2 : B3);
            float aV = fmaf(txf, aHi - aLo, aLo);
            float bV = fmaf(txf, bHi - bLo, bLo);
            float r = fmaf(aV, xin[k], bV);
            res[k] = fminf(fmaxf(r, 0.0f), 255.0f);
        }
        out4[q] = make_float4(res[0], res[1], res[2], res[3]);
    }
}

extern "C" void kernel_launch(void* const* d_in, const int* in_sizes, int n_in,
                              void* d_out, int out_size) {
    const float* x_lr = (const float*)d_in[0];
    const float* y_lr = (const float*)d_in[1];
    const float* x_hr = (const float*)d_in[2];
    float* out = (float*)d_out;

    dim3 g1(W_LR / TILE, H_LR / TILE, PLANES);   // (16,16,12)
    dim3 b1(32, 8);
    k1_ab_mean<<<g1, b1>>>(x_lr, y_lr);

    dim3 g2(H_HR, PLANES);                       // one block per output row
    k2_upsample_apply<<<g2, 256>>>(x_hr, out);
}

// round 4
// speedup vs baseline: 1.1287x; 1.0273x over previous
#include <cuda_runtime.h>

#define H_LR 512
#define W_LR 512
#define H_HR 2048
#define W_HR 2048
#define PLANES 12
#define EPS_F 0.01f

// Scratch for mean_A / mean_b at low resolution (alloc-free: __device__ globals)
__device__ float g_meanA[PLANES * H_LR * W_LR];
__device__ float g_meanB[PLANES * H_LR * W_LR];

#define TILE 32
#define SM_W 36   // TILE + 4 (2-pixel halo each side for double 3x3)
#define SM_A 34   // TILE + 2 (1-pixel apron of A/b)
#define SSTR 37   // row stride, avoids bank conflicts

__global__ __launch_bounds__(256)
void k1_ab_mean(const float* __restrict__ x, const float* __restrict__ y) {
    __shared__ float sx[SM_W * SSTR];
    __shared__ float sy[SM_W * SSTR];
    __shared__ float sA[SM_A * SSTR];
    __shared__ float sB[SM_A * SSTR];

    const int plane = blockIdx.z;
    const int gy0 = blockIdx.y * TILE;
    const int gx0 = blockIdx.x * TILE;
    const float* __restrict__ xp = x + (size_t)plane * (H_LR * W_LR);
    const float* __restrict__ yp = y + (size_t)plane * (H_LR * W_LR);
    const int t = threadIdx.y * 32 + threadIdx.x;
    const float inv9 = 1.0f / 9.0f;

    // Phase 1: load 36x36 halo with edge clamp
    for (int idx = t; idx < SM_W * SM_W; idx += 256) {
        int i = idx / SM_W, j = idx - i * SM_W;
        int gy = min(max(gy0 - 2 + i, 0), H_LR - 1);
        int gx = min(max(gx0 - 2 + j, 0), W_LR - 1);
        sx[i * SSTR + j] = xp[gy * W_LR + gx];
        sy[i * SSTR + j] = yp[gy * W_LR + gx];
    }
    __syncthreads();

    // Phase 2: compute A, b on the 34x34 apron, TWO horizontal outputs per
    // thread sharing a 3x4 tap window. A/b are evaluated at CLAMPED global
    // pixel coords (== replication padding of A for the second boxfilter).
    for (int idx = t; idx < SM_A * 17; idx += 256) {
        int i = idx / 17;
        int jp = idx - i * 17;
        int j0 = jp * 2;

        int py = min(max(gy0 - 1 + i, 0), H_LR - 1);
        int si = py - gy0 + 2;                       // [1,34]
        int px0 = min(max(gx0 - 1 + j0, 0), W_LR - 1);
        int px1 = min(max(gx0 + j0, 0), W_LR - 1);   // (gx0-1) + (j0+1)
        int sj0 = px0 - gx0 + 2;
        int sj1 = px1 - gx0 + 2;

        float cxs[4], cys[4], cxys[4], cxxs[4];
        #pragma unroll
        for (int c = 0; c < 4; c++) {
            int col = (c < 3) ? (sj0 - 1 + c) : (sj1 + 1);
            float xs = 0.f, ys = 0.f, xys = 0.f, xxs = 0.f;
            #pragma unroll
            for (int r = 0; r < 3; r++) {
                float xv = sx[(si - 1 + r) * SSTR + col];
                float yv = sy[(si - 1 + r) * SSTR + col];
                xs += xv; ys += yv;
                xys = fmaf(xv, yv, xys);
                xxs = fmaf(xv, xv, xxs);
            }
            cxs[c] = xs; cys[c] = ys; cxys[c] = xys; cxxs[c] = xxs;
        }

        bool two = (sj1 > sj0);
        float s0x  = cxs[0] + cxs[1] + cxs[2];
        float s0y  = cys[0] + cys[1] + cys[2];
        float s0xy = cxys[0] + cxys[1] + cxys[2];
        float s0xx = cxxs[0] + cxxs[1] + cxxs[2];
        float s1x  = two ? (cxs[1] + cxs[2] + cxs[3])   : s0x;
        float s1y  = two ? (cys[1] + cys[2] + cys[3])   : s0y;
        float s1xy = two ? (cxys[1] + cxys[2] + cxys[3]) : s0xy;
        float s1xx = two ? (cxxs[1] + cxxs[2] + cxxs[3]) : s0xx;

        float mx0 = s0x * inv9, my0 = s0y * inv9;
        float cov0 = s0xy * inv9 - mx0 * my0;
        float var0 = s0xx * inv9 - mx0 * mx0;
        float A0 = __fdividef(cov0, var0 + EPS_F);
        float B0 = my0 - A0 * mx0;

        float mx1 = s1x * inv9, my1 = s1y * inv9;
        float cov1 = s1xy * inv9 - mx1 * my1;
        float var1 = s1xx * inv9 - mx1 * mx1;
        float A1 = __fdividef(cov1, var1 + EPS_F);
        float B1 = my1 - A1 * mx1;

        sA[i * SSTR + j0] = A0;
        sB[i * SSTR + j0] = B0;
        sA[i * SSTR + j0 + 1] = A1;
        sB[i * SSTR + j0 + 1] = B1;
    }
    __syncthreads();

    // Phase 3a: horizontal 3-tap over A/b, store into reused sx/sy
    for (int idx = t; idx < SM_A * TILE; idx += 256) {
        int i = idx / TILE, j = idx - i * TILE;
        int o = i * SSTR + j;
        sx[o] = sA[o] + sA[o + 1] + sA[o + 2];
        sy[o] = sB[o] + sB[o + 1] + sB[o + 2];
    }
    __syncthreads();

    // Phase 3b: vertical 3-tap -> mean_A, mean_b, write to scratch
    const int tx = threadIdx.x;
    for (int ty = threadIdx.y; ty < TILE; ty += 8) {
        float sa = (sx[ty * SSTR + tx] + sx[(ty + 1) * SSTR + tx] + sx[(ty + 2) * SSTR + tx]) * inv9;
        float sb = (sy[ty * SSTR + tx] + sy[(ty + 1) * SSTR + tx] + sy[(ty + 2) * SSTR + tx]) * inv9;
        int o = plane * (H_LR * W_LR) + (gy0 + ty) * W_LR + (gx0 + tx);
        g_meanA[o] = sa;
        g_meanB[o] = sb;
    }
}

// Kernel 2: one block per output row. Stage vertically-lerped Ac/Bc (512 each)
// in SMEM; each thread handles 8 consecutive pixels spanning < 3 low-res
// units. Horizontal lerp done branch/select-free via the piecewise-linear
// closed form  aV(p) = A0 + D0*sat(p) + D1*sat(p-1) + D2*sat(p-2).
__global__ __launch_bounds__(256)
void k2_upsample_apply(const float* __restrict__ xhr, float* __restrict__ out) {
    __shared__ float sAc[W_LR];
    __shared__ float sBc[W_LR];

    const float SCALE = 511.0f / 2047.0f;
    const int plane = blockIdx.y;
    const int oy = blockIdx.x;
    const int t = threadIdx.x;

    float posy = (float)oy * SCALE;
    int iy0 = (int)posy;
    float tyf = posy - (float)iy0;
    int iy1 = min(iy0 + 1, H_LR - 1);

    const size_t pl = (size_t)plane * (H_LR * W_LR);
    if (t < 128) {
        const float4* r0 = (const float4*)(g_meanA + pl + iy0 * W_LR);
        const float4* r1 = (const float4*)(g_meanA + pl + iy1 * W_LR);
        float4 a0 = r0[t], a1 = r1[t];
        float4 ac;
        ac.x = fmaf(tyf, a1.x - a0.x, a0.x);
        ac.y = fmaf(tyf, a1.y - a0.y, a0.y);
        ac.z = fmaf(tyf, a1.z - a0.z, a0.z);
        ac.w = fmaf(tyf, a1.w - a0.w, a0.w);
        ((float4*)sAc)[t] = ac;
    } else {
        int u = t - 128;
        const float4* r0 = (const float4*)(g_meanB + pl + iy0 * W_LR);
        const float4* r1 = (const float4*)(g_meanB + pl + iy1 * W_LR);
        float4 b0 = r0[u], b1 = r1[u];
        float4 bc;
        bc.x = fmaf(tyf, b1.x - b0.x, b0.x);
        bc.y = fmaf(tyf, b1.y - b0.y, b0.y);
        bc.z = fmaf(tyf, b1.z - b0.z, b0.z);
        bc.w = fmaf(tyf, b1.w - b0.w, b0.w);
        ((float4*)sBc)[u] = bc;
    }
    __syncthreads();

    const int ox0 = t * 8;
    float posx0 = (float)ox0 * SCALE;
    int jb = (int)posx0;
    float f0 = posx0 - (float)jb;          // in [0,1)

    // 4 columns cover the whole 8-pixel group (max needed col = jb+3)
    int j3 = min(jb + 3, W_LR - 1);
    float A0 = sAc[jb], A1 = sAc[jb + 1], A2 = sAc[jb + 2], A3 = sAc[j3];
    float B0 = sBc[jb], B1 = sBc[jb + 1], B2 = sBc[jb + 2], B3 = sBc[j3];
    float DA0 = A1 - A0, DA1 = A2 - A1, DA2 = A3 - A2;
    float DB0 = B1 - B0, DB1 = B2 - B1, DB2 = B3 - B2;

    const size_t base = (size_t)plane * (H_HR * W_HR) + (size_t)oy * W_HR;
    const float4* __restrict__ xin4 = (const float4*)(xhr + base);
    float4* __restrict__ out4 = (float4*)(out + base);

    #pragma unroll
    for (int half = 0; half < 2; half++) {
        int q = t * 2 + half;
        float4 xv = xin4[q];
        float xin[4] = {xv.x, xv.y, xv.z, xv.w};
        float res[4];
        #pragma unroll
        for (int k = 0; k < 4; k++) {
            int kk = half * 4 + k;
            float p = fmaf((float)kk, SCALE, f0);   // in [0, 3)
            float t0 = __saturatef(p);
            float t1 = __saturatef(p - 1.0f);
            float t2 = __saturatef(p - 2.0f);
            float aV = fmaf(DA2, t2, fmaf(DA1, t1, fmaf(DA0, t0, A0)));
            float bV = fmaf(DB2, t2, fmaf(DB1, t1, fmaf(DB0, t0, B0)));
            float r = fmaf(aV, xin[k], bV);
            res[k] = fminf(fmaxf(r, 0.0f), 255.0f);
        }
        out4[q] = make_float4(res[0], res[1], res[2], res[3]);
    }
}

extern "C" void kernel_launch(void* const* d_in, const int* in_sizes, int n_in,
                              void* d_out, int out_size) {
    const float* x_lr = (const float*)d_in[0];
    const float* y_lr = (const float*)d_in[1];
    const float* x_hr = (const float*)d_in[2];
    float* out = (float*)d_out;

    dim3 g1(W_LR / TILE, H_LR / TILE, PLANES);   // (16,16,12)
    dim3 b1(32, 8);
    k1_ab_mean<<<g1, b1>>>(x_lr, y_lr);

    dim3 g2(H_HR, PLANES);                       // one block per output row
    k2_upsample_apply<<<g2, 256>>>(x_hr, out);
}

// round 5
// speedup vs baseline: 1.1291x; 1.0003x over previous
#include <cuda_runtime.h>

#define H_LR 512
#define W_LR 512
#define H_HR 2048
#define W_HR 2048
#define PLANES 12
#define EPS_F 0.01f

// Scratch for mean_A / mean_b at low resolution (alloc-free: __device__ globals)
__device__ float g_meanA[PLANES * H_LR * W_LR];
__device__ float g_meanB[PLANES * H_LR * W_LR];

#define TILE 32
#define SM_W 36   // TILE + 4 (2-pixel halo each side for double 3x3)
#define SM_A 34   // TILE + 2 (1-pixel apron of A/b)
#define SSTR 37   // row stride, avoids bank conflicts

__global__ __launch_bounds__(256)
void k1_ab_mean(const float* __restrict__ x, const float* __restrict__ y) {
    __shared__ float sx[SM_W * SSTR];
    __shared__ float sy[SM_W * SSTR];
    __shared__ float sA[SM_A * SSTR];
    __shared__ float sB[SM_A * SSTR];

    const int plane = blockIdx.z;
    const int gy0 = blockIdx.y * TILE;
    const int gx0 = blockIdx.x * TILE;
    const float* __restrict__ xp = x + (size_t)plane * (H_LR * W_LR);
    const float* __restrict__ yp = y + (size_t)plane * (H_LR * W_LR);
    const int t = threadIdx.y * 32 + threadIdx.x;
    const float inv9 = 1.0f / 9.0f;

    // Phase 1: load 36x36 halo with edge clamp
    for (int idx = t; idx < SM_W * SM_W; idx += 256) {
        int i = idx / SM_W, j = idx - i * SM_W;
        int gy = min(max(gy0 - 2 + i, 0), H_LR - 1);
        int gx = min(max(gx0 - 2 + j, 0), W_LR - 1);
        sx[i * SSTR + j] = xp[gy * W_LR + gx];
        sy[i * SSTR + j] = yp[gy * W_LR + gx];
    }
    __syncthreads();

    // Phase 2: compute A, b on the 34x34 apron, TWO horizontal outputs per
    // thread sharing a 3x4 tap window. A/b are evaluated at CLAMPED global
    // pixel coords (== replication padding of A for the second boxfilter).
    for (int idx = t; idx < SM_A * 17; idx += 256) {
        int i = idx / 17;
        int jp = idx - i * 17;
        int j0 = jp * 2;

        int py = min(max(gy0 - 1 + i, 0), H_LR - 1);
        int si = py - gy0 + 2;                       // [1,34]
        int px0 = min(max(gx0 - 1 + j0, 0), W_LR - 1);
        int px1 = min(max(gx0 + j0, 0), W_LR - 1);   // (gx0-1) + (j0+1)
        int sj0 = px0 - gx0 + 2;
        int sj1 = px1 - gx0 + 2;

        float cxs[4], cys[4], cxys[4], cxxs[4];
        #pragma unroll
        for (int c = 0; c < 4; c++) {
            int col = (c < 3) ? (sj0 - 1 + c) : (sj1 + 1);
            float xs = 0.f, ys = 0.f, xys = 0.f, xxs = 0.f;
            #pragma unroll
            for (int r = 0; r < 3; r++) {
                float xv = sx[(si - 1 + r) * SSTR + col];
                float yv = sy[(si - 1 + r) * SSTR + col];
                xs += xv; ys += yv;
                xys = fmaf(xv, yv, xys);
                xxs = fmaf(xv, xv, xxs);
            }
            cxs[c] = xs; cys[c] = ys; cxys[c] = xys; cxxs[c] = xxs;
        }

        bool two = (sj1 > sj0);
        float s0x  = cxs[0] + cxs[1] + cxs[2];
        float s0y  = cys[0] + cys[1] + cys[2];
        float s0xy = cxys[0] + cxys[1] + cxys[2];
        float s0xx = cxxs[0] + cxxs[1] + cxxs[2];
        float s1x  = two ? (cxs[1] + cxs[2] + cxs[3])   : s0x;
        float s1y  = two ? (cys[1] + cys[2] + cys[3])   : s0y;
        float s1xy = two ? (cxys[1] + cxys[2] + cxys[3]) : s0xy;
        float s1xx = two ? (cxxs[1] + cxxs[2] + cxxs[3]) : s0xx;

        float mx0 = s0x * inv9, my0 = s0y * inv9;
        float cov0 = s0xy * inv9 - mx0 * my0;
        float var0 = s0xx * inv9 - mx0 * mx0;
        float A0 = __fdividef(cov0, var0 + EPS_F);
        float B0 = my0 - A0 * mx0;

        float mx1 = s1x * inv9, my1 = s1y * inv9;
        float cov1 = s1xy * inv9 - mx1 * my1;
        float var1 = s1xx * inv9 - mx1 * mx1;
        float A1 = __fdividef(cov1, var1 + EPS_F);
        float B1 = my1 - A1 * mx1;

        sA[i * SSTR + j0] = A0;
        sB[i * SSTR + j0] = B0;
        sA[i * SSTR + j0 + 1] = A1;
        sB[i * SSTR + j0 + 1] = B1;
    }
    __syncthreads();

    // Phase 3a: horizontal 3-tap over A/b, store into reused sx/sy
    for (int idx = t; idx < SM_A * TILE; idx += 256) {
        int i = idx / TILE, j = idx - i * TILE;
        int o = i * SSTR + j;
        sx[o] = sA[o] + sA[o + 1] + sA[o + 2];
        sy[o] = sB[o] + sB[o + 1] + sB[o + 2];
    }
    __syncthreads();

    // Phase 3b: vertical 3-tap -> mean_A, mean_b, write to scratch
    const int tx = threadIdx.x;
    for (int ty = threadIdx.y; ty < TILE; ty += 8) {
        float sa = (sx[ty * SSTR + tx] + sx[(ty + 1) * SSTR + tx] + sx[(ty + 2) * SSTR + tx]) * inv9;
        float sb = (sy[ty * SSTR + tx] + sy[(ty + 1) * SSTR + tx] + sy[(ty + 2) * SSTR + tx]) * inv9;
        int o = plane * (H_LR * W_LR) + (gy0 + ty) * W_LR + (gx0 + tx);
        g_meanA[o] = sa;
        g_meanB[o] = sb;
    }
}

// Kernel 2: one block per output row. Stage vertically-lerped Ac/Bc (512 each)
// in SMEM; each thread handles 8 consecutive pixels spanning < 3 low-res
// units. Horizontal lerp done branch/select-free via the piecewise-linear
// closed form  aV(p) = A0 + D0*sat(p) + D1*sat(p-1) + D2*sat(p-2).
__global__ __launch_bounds__(256)
void k2_upsample_apply(const float* __restrict__ xhr, float* __restrict__ out) {
    __shared__ float sAc[W_LR];
    __shared__ float sBc[W_LR];

    const float SCALE = 511.0f / 2047.0f;
    const int plane = blockIdx.y;
    const int oy = blockIdx.x;
    const int t = threadIdx.x;

    float posy = (float)oy * SCALE;
    int iy0 = (int)posy;
    float tyf = posy - (float)iy0;
    int iy1 = min(iy0 + 1, H_LR - 1);

    const size_t pl = (size_t)plane * (H_LR * W_LR);
    if (t < 128) {
        const float4* r0 = (const float4*)(g_meanA + pl + iy0 * W_LR);
        const float4* r1 = (const float4*)(g_meanA + pl + iy1 * W_LR);
        float4 a0 = r0[t], a1 = r1[t];
        float4 ac;
        ac.x = fmaf(tyf, a1.x - a0.x, a0.x);
        ac.y = fmaf(tyf, a1.y - a0.y, a0.y);
        ac.z = fmaf(tyf, a1.z - a0.z, a0.z);
        ac.w = fmaf(tyf, a1.w - a0.w, a0.w);
        ((float4*)sAc)[t] = ac;
    } else {
        int u = t - 128;
        const float4* r0 = (const float4*)(g_meanB + pl + iy0 * W_LR);
        const float4* r1 = (const float4*)(g_meanB + pl + iy1 * W_LR);
        float4 b0 = r0[u], b1 = r1[u];
        float4 bc;
        bc.x = fmaf(tyf, b1.x - b0.x, b0.x);
        bc.y = fmaf(tyf, b1.y - b0.y, b0.y);
        bc.z = fmaf(tyf, b1.z - b0.z, b0.z);
        bc.w = fmaf(tyf, b1.w - b0.w, b0.w);
        ((float4*)sBc)[u] = bc;
    }
    __syncthreads();

    const int ox0 = t * 8;
    float posx0 = (float)ox0 * SCALE;
    int jb = (int)posx0;
    float f0 = posx0 - (float)jb;          // in [0,1)

    // 4 columns cover the whole 8-pixel group (max needed col = jb+3)
    int j3 = min(jb + 3, W_LR - 1);
    float A0 = sAc[jb], A1 = sAc[jb + 1], A2 = sAc[jb + 2], A3 = sAc[j3];
    float B0 = sBc[jb], B1 = sBc[jb + 1], B2 = sBc[jb + 2], B3 = sBc[j3];
    float DA0 = A1 - A0, DA1 = A2 - A1, DA2 = A3 - A2;
    float DB0 = B1 - B0, DB1 = B2 - B1, DB2 = B3 - B2;

    const size_t base = (size_t)plane * (H_HR * W_HR) + (size_t)oy * W_HR;
    const float4* __restrict__ xin4 = (const float4*)(xhr + base);
    float4* __restrict__ out4 = (float4*)(out + base);

    #pragma unroll
    for (int half = 0; half < 2; half++) {
        int q = t * 2 + half;
        float4 xv = xin4[q];
        float xin[4] = {xv.x, xv.y, xv.z, xv.w};
        float res[4];
        #pragma unroll
        for (int k = 0; k < 4; k++) {
            int kk = half * 4 + k;
            float p = fmaf((float)kk, SCALE, f0);   // in [0, 3)
            float t0 = __saturatef(p);
            float t1 = __saturatef(p - 1.0f);
            float t2 = __saturatef(p - 2.0f);
            float aV = fmaf(DA2, t2, fmaf(DA1, t1, fmaf(DA0, t0, A0)));
            float bV = fmaf(DB2, t2, fmaf(DB1, t1, fmaf(DB0, t0, B0)));
            float r = fmaf(aV, xin[k], bV);
            res[k] = fminf(fmaxf(r, 0.0f), 255.0f);
        }
        out4[q] = make_float4(res[0], res[1], res[2], res[3]);
    }
}

extern "C" void kernel_launch(void* const* d_in, const int* in_sizes, int n_in,
                              void* d_out, int out_size) {
    const float* x_lr = (const float*)d_in[0];
    const float* y_lr = (const float*)d_in[1];
    const float* x_hr = (const float*)d_in[2];
    float* out = (float*)d_out;

    dim3 g1(W_LR / TILE, H_LR / TILE, PLANES);   // (16,16,12)
    dim3 b1(32, 8);
    k1_ab_mean<<<g1, b1>>>(x_lr, y_lr);

    dim3 g2(H_HR, PLANES);                       // one block per output row
    k2_upsample_apply<<<g2, 256>>>(x_hr, out);
}